// round 1
// baseline (speedup 1.0000x reference)
#include <cuda_runtime.h>
#include <cstdint>

// data_share_block: out[c,t,x,y] =
//   m_cur            ?  k[c,t]        :
//   m_prev           ?  ALPHA*k[c,t-1]:
//   m_next           ?  BETA *k[c,t+1]: 0
// (nested form is exact: the three reference terms are mutually exclusive)
//
// Rolling-register walk along t: each k element read exactly once (float4),
// mask re-read per channel but L2-resident (16 MiB total).

#define ALPHA 0.5f
#define BETA  0.25f

constexpr int NC = 32;
constexpr int NT = 64;
constexpr int NX = 256;
constexpr int NY = 256;
constexpr int PLANE4  = NX * NY / 4;   // float4s per t-slice = 16384
constexpr int COLS    = NC * PLANE4;   // total threads = 524288

__global__ void __launch_bounds__(256, 8)
dsb_kernel(const float4* __restrict__ k,
           const int4*   __restrict__ mask,
           float4*       __restrict__ out)
{
    const int gid = blockIdx.x * blockDim.x + threadIdx.x;
    if (gid >= COLS) return;

    const int xy4 = gid & (PLANE4 - 1);     // position within a t-slice (float4 units)
    const int c   = gid >> 14;              // gid / PLANE4

    const float4* kk = k   + (size_t)c * NT * PLANE4 + xy4;
    float4*       oo = out + (size_t)c * NT * PLANE4 + xy4;
    const int4*   mm = mask + xy4;

    float4 kp = make_float4(0.f, 0.f, 0.f, 0.f);
    int4   mp = make_int4(0, 0, 0, 0);
    float4 kc = kk[0];
    int4   mc = mm[0];

    #pragma unroll 4
    for (int t = 0; t < NT; t++) {
        float4 kn;
        int4   mn;
        if (t < NT - 1) {
            kn = kk[(t + 1) * PLANE4];
            mn = mm[(t + 1) * PLANE4];
        } else {
            kn = make_float4(0.f, 0.f, 0.f, 0.f);
            mn = make_int4(0, 0, 0, 0);
        }

        float4 o;
        o.x = mc.x ? kc.x : (mp.x ? ALPHA * kp.x : (mn.x ? BETA * kn.x : 0.f));
        o.y = mc.y ? kc.y : (mp.y ? ALPHA * kp.y : (mn.y ? BETA * kn.y : 0.f));
        o.z = mc.z ? kc.z : (mp.z ? ALPHA * kp.z : (mn.z ? BETA * kn.z : 0.f));
        o.w = mc.w ? kc.w : (mp.w ? ALPHA * kp.w : (mn.w ? BETA * kn.w : 0.f));

        oo[t * PLANE4] = o;

        kp = kc; mp = mc;
        kc = kn; mc = mn;
    }
}

extern "C" void kernel_launch(void* const* d_in, const int* in_sizes, int n_in,
                              void* d_out, int out_size)
{
    const float4* k    = (const float4*)d_in[0];
    const int4*   mask = (const int4*)d_in[1];
    float4*       out  = (float4*)d_out;

    const int threads = 256;
    const int blocks  = (COLS + threads - 1) / threads;   // 2048
    dsb_kernel<<<blocks, threads>>>(k, mask, out);
}

// round 2
// speedup vs baseline: 1.1132x; 1.1132x over previous
#include <cuda_runtime.h>
#include <cstdint>

// out[c,t,x,y] = mc ? k[t] : mp ? 0.5*k[t-1] : mn3 ? 0.25*k[t+1] : 0
// where the 3 cases are mutually exclusive. Mask is channel-invariant, so we
// precompute a 2-bit selector per (t, xy) into a 1 MB L2-resident table, then
// the main kernel is a pure 1-load/1-store stream with register rolling over t.

#define ALPHA 0.5f
#define BETA  0.25f

constexpr int NC = 32;
constexpr int NT = 64;
constexpr int PLANE4 = 256 * 256 / 4;     // 16384 float4 groups per t-slice
constexpr int COLS   = NC * PLANE4;       // 524288 threads in main kernel

// Selector table: [chunk q = t/16][group g], uint4 = 16 t-steps * (4 lanes * 2 bits)
// byte layout: byte (t%4) of word (t%16)/4 holds codes: lane0 bits[0:2] ... lane3 bits[6:8]
__device__ uint4 g_sel[4][PLANE4];

__device__ __forceinline__ uint32_t code1(int mc, int mp, int mn) {
    return mc ? 1u : (mp ? 2u : (mn ? 3u : 0u));
}

__global__ void __launch_bounds__(256)
pre_kernel(const int4* __restrict__ mask)
{
    const int g = blockIdx.x * blockDim.x + threadIdx.x;   // 0..16383
    if (g >= PLANE4) return;

    int4 mp = make_int4(0, 0, 0, 0);
    int4 mc = mask[g];
    uint32_t w[16];
    #pragma unroll
    for (int i = 0; i < 16; i++) w[i] = 0u;

    #pragma unroll
    for (int t = 0; t < NT; t++) {
        int4 mn = (t < NT - 1) ? mask[(t + 1) * PLANE4 + g] : make_int4(0, 0, 0, 0);
        uint32_t byte =  code1(mc.x, mp.x, mn.x)
                      | (code1(mc.y, mp.y, mn.y) << 2)
                      | (code1(mc.z, mp.z, mn.z) << 4)
                      | (code1(mc.w, mp.w, mn.w) << 6);
        w[t >> 2] |= byte << ((t & 3) * 8);
        mp = mc; mc = mn;
    }
    #pragma unroll
    for (int q = 0; q < 4; q++)
        g_sel[q][g] = make_uint4(w[4 * q], w[4 * q + 1], w[4 * q + 2], w[4 * q + 3]);
}

__device__ __forceinline__ float pick(uint32_t c, float kc, float kp, float kn) {
    return (c == 1u) ? kc
         : (c == 2u) ? ALPHA * kp
         : (c == 3u) ? BETA * kn
         : 0.0f;
}

__global__ void __launch_bounds__(256, 8)
dsb_kernel(const float4* __restrict__ k, float4* __restrict__ out)
{
    const int gid = blockIdx.x * blockDim.x + threadIdx.x;
    if (gid >= COLS) return;

    const int g = gid & (PLANE4 - 1);
    const int c = gid >> 14;

    const float4* kk = k   + (size_t)c * NT * PLANE4 + g;
    float4*       oo = out + (size_t)c * NT * PLANE4 + g;

    float4 kp = make_float4(0.f, 0.f, 0.f, 0.f);
    float4 kc = __ldcs(kk);
    float4 kn = kp;

    int t = 0;
    #pragma unroll 1
    for (int q = 0; q < 4; q++) {
        const uint4 s = g_sel[q][g];
        uint32_t words[4] = { s.x, s.y, s.z, s.w };
        #pragma unroll
        for (int j = 0; j < 4; j++) {
            const uint32_t wrd = words[j];
            #pragma unroll
            for (int tt = 0; tt < 4; tt++) {
                if (t < NT - 1) kn = __ldcs(kk + (t + 1) * PLANE4);

                const uint32_t byte = (wrd >> (tt * 8)) & 0xFFu;
                float4 o;
                o.x = pick( byte       & 3u, kc.x, kp.x, kn.x);
                o.y = pick((byte >> 2) & 3u, kc.y, kp.y, kn.y);
                o.z = pick((byte >> 4) & 3u, kc.z, kp.z, kn.z);
                o.w = pick((byte >> 6) & 3u, kc.w, kp.w, kn.w);

                __stcs(oo + t * PLANE4, o);

                kp = kc; kc = kn;
                t++;
            }
        }
    }
}

extern "C" void kernel_launch(void* const* d_in, const int* in_sizes, int n_in,
                              void* d_out, int out_size)
{
    const float4* k    = (const float4*)d_in[0];
    const int4*   mask = (const int4*)d_in[1];
    float4*       out  = (float4*)d_out;

    pre_kernel<<<PLANE4 / 256, 256>>>(mask);
    dsb_kernel<<<COLS / 256, 256>>>(k, out);
}

// round 3
// speedup vs baseline: 1.1697x; 1.0508x over previous
#include <cuda_runtime.h>
#include <cstdint>

// out[c,t,x,y] = mc ? k[t] : mp ? 0.5*k[t-1] : mn ? 0.25*k[t+1] : 0   (cases exclusive)
// Mask is channel-invariant -> precompute 2-bit selector per (t, xy) into a
// 1 MB L2-resident table. Main kernel: pure 1-load/1-store stream, rolling
// registers over t with a 2-stage prefetch pipeline (load k[t+2] while
// computing o(t)).

#define ALPHA 0.5f
#define BETA  0.25f

constexpr int NC = 32;
constexpr int NT = 64;
constexpr int PLANE4 = 256 * 256 / 4;     // 16384 float4 groups per t-slice
constexpr int COLS   = NC * PLANE4;       // 524288 threads in main kernel

// g_sel[q][g]: uint4 packing 16 t-steps (t = 16q .. 16q+15), 4 lanes * 2 bits each.
__device__ uint4 g_sel[4][PLANE4];

__device__ __forceinline__ uint32_t code1(int mc, int mp, int mn) {
    return mc ? 1u : (mp ? 2u : (mn ? 3u : 0u));
}

// One thread per (q, g): computes 16 t-steps. Reads mask[16q-1 .. 16q+16].
__global__ void __launch_bounds__(256)
pre_kernel(const int4* __restrict__ mask)
{
    const int tidg = blockIdx.x * blockDim.x + threadIdx.x;   // 0 .. 4*PLANE4-1
    const int g = tidg & (PLANE4 - 1);
    const int q = tidg >> 14;
    const int t0 = q * 16;

    int4 mp = (t0 > 0) ? mask[(t0 - 1) * PLANE4 + g] : make_int4(0, 0, 0, 0);
    int4 mc = mask[t0 * PLANE4 + g];

    uint32_t w[4] = {0u, 0u, 0u, 0u};

    #pragma unroll
    for (int i = 0; i < 16; i++) {
        const int t = t0 + i;
        int4 mn = (t < NT - 1) ? mask[(t + 1) * PLANE4 + g] : make_int4(0, 0, 0, 0);
        uint32_t byte =  code1(mc.x, mp.x, mn.x)
                      | (code1(mc.y, mp.y, mn.y) << 2)
                      | (code1(mc.z, mp.z, mn.z) << 4)
                      | (code1(mc.w, mp.w, mn.w) << 6);
        w[i >> 2] |= byte << ((i & 3) * 8);
        mp = mc; mc = mn;
    }
    g_sel[q][g] = make_uint4(w[0], w[1], w[2], w[3]);
}

__device__ __forceinline__ float pick(uint32_t c, float kc, float kp, float kn) {
    return (c == 1u) ? kc
         : (c == 2u) ? ALPHA * kp
         : (c == 3u) ? BETA * kn
         : 0.0f;
}

__global__ void __launch_bounds__(256)
dsb_kernel(const float4* __restrict__ k, float4* __restrict__ out)
{
    const int gid = blockIdx.x * blockDim.x + threadIdx.x;
    const int g = gid & (PLANE4 - 1);
    const int c = gid >> 14;

    const float4* kk = k   + (size_t)c * NT * PLANE4 + g;
    float4*       oo = out + (size_t)c * NT * PLANE4 + g;

    const float4 zero = make_float4(0.f, 0.f, 0.f, 0.f);
    float4 kp = zero;
    float4 kc = __ldcs(kk);
    float4 kn = __ldcs(kk + PLANE4);

    int t = 0;
    #pragma unroll 1
    for (int q = 0; q < 4; q++) {
        const uint4 s = g_sel[q][g];
        uint32_t words[4] = { s.x, s.y, s.z, s.w };
        #pragma unroll
        for (int j = 0; j < 4; j++) {
            const uint32_t wrd = words[j];
            #pragma unroll
            for (int tt = 0; tt < 4; tt++) {
                // prefetch k[t+2] (used as kn in the NEXT iteration)
                float4 kf = (t < NT - 2) ? __ldcs(kk + (t + 2) * PLANE4) : zero;

                const uint32_t byte = (wrd >> (tt * 8)) & 0xFFu;
                float4 o;
                o.x = pick( byte       & 3u, kc.x, kp.x, kn.x);
                o.y = pick((byte >> 2) & 3u, kc.y, kp.y, kn.y);
                o.z = pick((byte >> 4) & 3u, kc.z, kp.z, kn.z);
                o.w = pick((byte >> 6) & 3u, kc.w, kp.w, kn.w);

                __stcs(oo + t * PLANE4, o);

                kp = kc; kc = kn; kn = kf;
                t++;
            }
        }
    }
}

extern "C" void kernel_launch(void* const* d_in, const int* in_sizes, int n_in,
                              void* d_out, int out_size)
{
    const float4* k    = (const float4*)d_in[0];
    const int4*   mask = (const int4*)d_in[1];
    float4*       out  = (float4*)d_out;

    pre_kernel<<<(4 * PLANE4) / 256, 256>>>(mask);
    dsb_kernel<<<COLS / 256, 256>>>(k, out);
}

// round 4
// speedup vs baseline: 1.1994x; 1.0253x over previous
#include <cuda_runtime.h>
#include <cstdint>

// out[c,t,x,y] = mc ? k[t] : mp ? 0.5*k[t-1] : mn ? 0.25*k[t+1] : 0   (cases exclusive)
// Mask is channel-invariant -> precompute 2-bit selector per (t, xy) into a
// 1 MB L2-resident table. Main kernel: pure 1-load/1-store rolling stream.

#define ALPHA 0.5f
#define BETA  0.25f

constexpr int NC = 32;
constexpr int NT = 64;
constexpr int PLANE4 = 256 * 256 / 4;     // 16384 float4 groups per t-slice
constexpr int COLS   = NC * PLANE4;       // 524288 threads in main kernel

// g_sel viewed as [4][PLANE4] uint4 by dsb; written as uint32 words by pre.
// word index w (0..15) holds t = 4w..4w+3; uint4 q of dsb covers words 4q..4q+3.
__device__ uint4 g_sel[4][PLANE4];

__device__ __forceinline__ uint32_t code1(int mc, int mp, int mn) {
    return mc ? 1u : (mp ? 2u : (mn ? 3u : 0u));
}

// One thread per (h, g), h = 0..7: computes 8 t-steps = 2 uint32 words.
// Reads mask[8h-1 .. 8h+8] (10 int4 loads), writes 2 words.
__global__ void __launch_bounds__(256)
pre_kernel(const int4* __restrict__ mask)
{
    const int tidg = blockIdx.x * blockDim.x + threadIdx.x;   // 0 .. 8*PLANE4-1
    const int g = tidg & (PLANE4 - 1);
    const int h = tidg >> 14;           // 0..7
    const int t0 = h * 8;

    int4 mbuf[10];
    #pragma unroll
    for (int i = 0; i < 10; i++) {
        const int t = t0 - 1 + i;
        mbuf[i] = (t >= 0 && t < NT) ? __ldg(&mask[t * PLANE4 + g])
                                     : make_int4(0, 0, 0, 0);
    }

    uint32_t w[2] = {0u, 0u};
    #pragma unroll
    for (int i = 0; i < 8; i++) {
        const int4 mp = mbuf[i];
        const int4 mc = mbuf[i + 1];
        const int4 mn = mbuf[i + 2];
        uint32_t byte =  code1(mc.x, mp.x, mn.x)
                      | (code1(mc.y, mp.y, mn.y) << 2)
                      | (code1(mc.z, mp.z, mn.z) << 4)
                      | (code1(mc.w, mp.w, mn.w) << 6);
        w[i >> 2] |= byte << ((i & 3) * 8);
    }

    // flat word index: word = 2h..2h+1 ; uint4 chunk q = word/4, component word%4
    uint32_t* sel_words = reinterpret_cast<uint32_t*>(g_sel);
    const int w0 = 2 * h;
    // layout of g_sel[q][g].{x,y,z,w} flattened: ((q*PLANE4 + g)*4 + comp)
    sel_words[(( (w0    ) >> 2) * PLANE4 + g) * 4 + ((w0    ) & 3)] = w[0];
    sel_words[(( (w0 + 1) >> 2) * PLANE4 + g) * 4 + ((w0 + 1) & 3)] = w[1];
}

__device__ __forceinline__ float pick(uint32_t c, float kc, float kp, float kn) {
    return (c == 1u) ? kc
         : (c == 2u) ? ALPHA * kp
         : (c == 3u) ? BETA * kn
         : 0.0f;
}

__global__ void __launch_bounds__(256, 8)
dsb_kernel(const float4* __restrict__ k, float4* __restrict__ out)
{
    const int gid = blockIdx.x * blockDim.x + threadIdx.x;
    const int g = gid & (PLANE4 - 1);
    const int c = gid >> 14;

    const float4* kk = k   + (size_t)c * NT * PLANE4 + g;
    float4*       oo = out + (size_t)c * NT * PLANE4 + g;

    float4 kp = make_float4(0.f, 0.f, 0.f, 0.f);
    float4 kc = __ldcs(kk);

    int t = 0;
    #pragma unroll 1
    for (int q = 0; q < 4; q++) {
        const uint4 s = g_sel[q][g];
        uint32_t words[4] = { s.x, s.y, s.z, s.w };
        #pragma unroll
        for (int j = 0; j < 4; j++) {
            const uint32_t wrd = words[j];
            #pragma unroll
            for (int tt = 0; tt < 4; tt++) {
                float4 kn = (t < NT - 1) ? __ldcs(kk + (t + 1) * PLANE4)
                                         : make_float4(0.f, 0.f, 0.f, 0.f);

                const uint32_t byte = (wrd >> (tt * 8)) & 0xFFu;
                float4 o;
                o.x = pick( byte       & 3u, kc.x, kp.x, kn.x);
                o.y = pick((byte >> 2) & 3u, kc.y, kp.y, kn.y);
                o.z = pick((byte >> 4) & 3u, kc.z, kp.z, kn.z);
                o.w = pick((byte >> 6) & 3u, kc.w, kp.w, kn.w);

                __stcs(oo + t * PLANE4, o);

                kp = kc; kc = kn;
                t++;
            }
        }
    }
}

extern "C" void kernel_launch(void* const* d_in, const int* in_sizes, int n_in,
                              void* d_out, int out_size)
{
    const float4* k    = (const float4*)d_in[0];
    const int4*   mask = (const int4*)d_in[1];
    float4*       out  = (float4*)d_out;

    pre_kernel<<<(8 * PLANE4) / 256, 256>>>(mask);
    dsb_kernel<<<COLS / 256, 256>>>(k, out);
}

// round 5
// speedup vs baseline: 1.2052x; 1.0049x over previous
#include <cuda_runtime.h>
#include <cstdint>

// out[c,t,x,y] = mc ? k[t] : mp ? 0.5*k[t-1] : mn ? 0.25*k[t+1] : 0   (cases exclusive)
// Mask is channel-invariant -> precompute 2-bit selector per (t, xy) into a
// 1 MB L2-resident word-major table sel[word][g]; word w packs t = 4w..4w+3
// (4 lanes * 2 bits per t). Main kernel: pure 1-load/1-store rolling stream.

#define ALPHA 0.5f
#define BETA  0.25f

constexpr int NC = 32;
constexpr int NT = 64;
constexpr int PLANE4 = 256 * 256 / 4;     // 16384 float4 groups per t-slice
constexpr int COLS   = NC * PLANE4;       // 524288 threads in main kernel
constexpr int NWORDS = NT / 4;            // 16 selector words per g

__device__ uint32_t g_sel[NWORDS * PLANE4];   // [word][g], 1 MB

__device__ __forceinline__ uint32_t code1(int mc, int mp, int mn) {
    return mc ? 1u : (mp ? 2u : (mn ? 3u : 0u));
}

// One thread per (word w, g): computes 4 t-steps (t = 4w..4w+3).
// Reads mask[4w-1 .. 4w+4] (6 coalesced int4 loads), writes 1 coalesced word.
__global__ void __launch_bounds__(256)
pre_kernel(const int4* __restrict__ mask)
{
    const int tidg = blockIdx.x * blockDim.x + threadIdx.x;  // 0 .. NWORDS*PLANE4-1
    const int g = tidg & (PLANE4 - 1);
    const int w = tidg >> 14;            // 0..15
    const int t0 = w * 4;

    int4 mbuf[6];
    #pragma unroll
    for (int i = 0; i < 6; i++) {
        const int t = t0 - 1 + i;
        mbuf[i] = (t >= 0 && t < NT) ? __ldg(&mask[t * PLANE4 + g])
                                     : make_int4(0, 0, 0, 0);
    }

    uint32_t word = 0u;
    #pragma unroll
    for (int i = 0; i < 4; i++) {
        const int4 mp = mbuf[i];
        const int4 mc = mbuf[i + 1];
        const int4 mn = mbuf[i + 2];
        uint32_t byte =  code1(mc.x, mp.x, mn.x)
                      | (code1(mc.y, mp.y, mn.y) << 2)
                      | (code1(mc.z, mp.z, mn.z) << 4)
                      | (code1(mc.w, mp.w, mn.w) << 6);
        word |= byte << (i * 8);
    }

    g_sel[w * PLANE4 + g] = word;        // fully coalesced 4B stores
}

__device__ __forceinline__ float pick(uint32_t c, float kc, float kp, float kn) {
    return (c == 1u) ? kc
         : (c == 2u) ? ALPHA * kp
         : (c == 3u) ? BETA * kn
         : 0.0f;
}

__global__ void __launch_bounds__(256, 8)
dsb_kernel(const float4* __restrict__ k, float4* __restrict__ out)
{
    const int gid = blockIdx.x * blockDim.x + threadIdx.x;
    const int g = gid & (PLANE4 - 1);
    const int c = gid >> 14;

    const float4* kk = k   + (size_t)c * NT * PLANE4 + g;
    float4*       oo = out + (size_t)c * NT * PLANE4 + g;

    float4 kp = make_float4(0.f, 0.f, 0.f, 0.f);
    float4 kc = __ldcs(kk);

    int t = 0;
    #pragma unroll 1
    for (int w = 0; w < NWORDS; w++) {
        const uint32_t wrd = __ldg(&g_sel[w * PLANE4 + g]);   // L2-resident
        #pragma unroll
        for (int tt = 0; tt < 4; tt++) {
            float4 kn = (t < NT - 1) ? __ldcs(kk + (t + 1) * PLANE4)
                                     : make_float4(0.f, 0.f, 0.f, 0.f);

            const uint32_t byte = (wrd >> (tt * 8)) & 0xFFu;
            float4 o;
            o.x = pick( byte       & 3u, kc.x, kp.x, kn.x);
            o.y = pick((byte >> 2) & 3u, kc.y, kp.y, kn.y);
            o.z = pick((byte >> 4) & 3u, kc.z, kp.z, kn.z);
            o.w = pick((byte >> 6) & 3u, kc.w, kp.w, kn.w);

            __stcs(oo + t * PLANE4, o);

            kp = kc; kc = kn;
            t++;
        }
    }
}

extern "C" void kernel_launch(void* const* d_in, const int* in_sizes, int n_in,
                              void* d_out, int out_size)
{
    const float4* k    = (const float4*)d_in[0];
    const int4*   mask = (const int4*)d_in[1];
    float4*       out  = (float4*)d_out;

    pre_kernel<<<(NWORDS * PLANE4) / 256, 256>>>(mask);
    dsb_kernel<<<COLS / 256, 256>>>(k, out);
}